// round 8
// baseline (speedup 1.0000x reference)
#include <cuda_runtime.h>

// residual = K3 * (K2 * (K1 * x)), depthwise, per-stage zero padding.
// Register-rolling column-strip kernel:
//   - thread t owns output cols [4t, 4t+4); 128 threads = full 512 width
//   - block sweeps a 64-row band; all intermediates live in registers
//   - K1 = S(x)S - 2 D(x)D  (S=[1,2,1], D=[1,0,1])        -> edge row
//   - K2 = A(x)r0 + B(x)r1  (A=[1,0,-2,0,1], B=[0,1,-2,1,0],
//          r0=[-1,2,-2,2,-1], r1=[2,-6,8,-6,2])           -> H0/H1 + vertical scatter
//   - K3 = [1,-2,1] horizontal at finalize
// Rings: R[5][12] input rows, TA[5][6] tex accumulators; unroll 5 => static indices.

#define IMG   512
#define BAND  64
#define NTH   128

// Load input row ROW (cols cx-4 .. cx+7) into DST[12]; zero outside image.
#define LOADROW(DST, ROW) do {                                                  \
    const float4 _z = make_float4(0.f, 0.f, 0.f, 0.f);                         \
    const bool _rok = ((unsigned)(ROW) < IMG);                                  \
    float4 _va = (_rok && okL) ? *reinterpret_cast<const float4*>(rowp)     : _z; \
    float4 _vb =  _rok         ? *reinterpret_cast<const float4*>(rowp + 4) : _z; \
    float4 _vc = (_rok && okR) ? *reinterpret_cast<const float4*>(rowp + 8) : _z; \
    DST[0]=_va.x; DST[1]=_va.y; DST[2]=_va.z; DST[3]=_va.w;                     \
    DST[4]=_vb.x; DST[5]=_vb.y; DST[6]=_vb.z; DST[7]=_vb.w;                     \
    DST[8]=_vc.x; DST[9]=_vc.y; DST[10]=_vc.z; DST[11]=_vc.w;                   \
    rowp += IMG; } while (0)

// One pipeline step. U = t%5 (literal). TOPS/MIDS: ring slots of rows e-1, e.
// S1..S4 = (U+1..U+4)%5 (literal) for the TA scatter.
#define STEP(U, TOPS, MIDS, S1, S2, S3, S4) do {                                \
    const int t = tt + (U);                                                     \
    const int e = Y0 - 2 + t;              /* edge row index */                 \
    LOADROW(R[U], e + 1);                  /* bot = row e+1 -> slot U */        \
    if ((unsigned)e < IMG && t <= 67) {                                         \
        float SY[12], DY[12];                                                   \
        _Pragma("unroll")                                                       \
        for (int c = 0; c < 12; c++) {                                          \
            float tb = fmaf(1.f, R[TOPS][c], R[U][c]);                          \
            DY[c] = tb;                                                         \
            SY[c] = fmaf(2.f, R[MIDS][c], tb);                                  \
        }                                                                       \
        float E[10];                                                            \
        _Pragma("unroll")                                                       \
        for (int j = 0; j < 10; j++) {                                          \
            float sv = fmaf(2.f, SY[j+1], fmaf(1.f, SY[j], SY[j+2]));           \
            E[j] = fmaf(-2.f, fmaf(1.f, DY[j], DY[j+2]), sv);                   \
        }                                                                       \
        if (tid == 0)          { E[0] = 0.f; E[1] = 0.f; E[2] = 0.f; }          \
        else if (tid == NTH-1) { E[7] = 0.f; E[8] = 0.f; E[9] = 0.f; }          \
        _Pragma("unroll")                                                       \
        for (int c = 0; c < 6; c++) {                                           \
            float s1 = fmaf(1.f, E[c],   E[c+4]);                               \
            float s2 = fmaf(1.f, E[c+1], E[c+3]);                               \
            float H0 = fmaf(-2.f, E[c+2], fmaf( 2.f, s2, -s1));                 \
            float Hh = fmaf( 4.f, E[c+2], fmaf(-3.f, s2,  s1)); /* = H1/2 */    \
            TA[U][c]  = fmaf( 1.f, H0, TA[U][c]);           /* y = e-2 */       \
            TA[S1][c] = fmaf( 2.f, Hh, TA[S1][c]);          /* y = e-1 */       \
            TA[S2][c] = fmaf(-2.f, H0, fmaf(-4.f, Hh, TA[S2][c])); /* y=e */    \
            TA[S3][c] = fmaf( 2.f, Hh, TA[S3][c]);          /* y = e+1 */       \
            TA[S4][c] = fmaf( 1.f, H0, TA[S4][c]);          /* y = e+2 */       \
        }                                                                       \
    }                                                                           \
    { /* finalize output row y = Y0-4+t (slot U), then recycle the slot */      \
        float tv0 = okL ? TA[U][0] : 0.f;   /* tex zero-pad at image cols */    \
        float tv5 = okR ? TA[U][5] : 0.f;                                       \
        if ((unsigned)(t - 4) <= 63u) {                                         \
            float4 o;                                                           \
            o.x = fmaf(-2.f, TA[U][1], fmaf(1.f, tv0,      TA[U][2]));          \
            o.y = fmaf(-2.f, TA[U][2], fmaf(1.f, TA[U][1], TA[U][3]));          \
            o.z = fmaf(-2.f, TA[U][3], fmaf(1.f, TA[U][2], TA[U][4]));          \
            o.w = fmaf(-2.f, TA[U][4], fmaf(1.f, TA[U][3], tv5));               \
            *reinterpret_cast<float4*>(op) = o;                                 \
        }                                                                       \
        op += IMG;                                                              \
        _Pragma("unroll")                                                       \
        for (int c = 0; c < 6; c++) TA[U][c] = 0.f;                             \
    } } while (0)

__global__ __launch_bounds__(NTH, 3)
void residual_feature_kernel(const float* __restrict__ x, float* __restrict__ out)
{
    const int tid = threadIdx.x;
    const int Y0  = blockIdx.x * BAND;
    const long base = (long)blockIdx.y * (IMG * IMG);
    const int cx  = tid * 4;
    const bool okL = (tid != 0);
    const bool okR = (tid != NTH - 1);

    float R[5][12];     // input-row ring (cols cx-4 .. cx+7)
    float TA[5][6];     // tex accumulator ring (cols cx-1 .. cx+4)
#pragma unroll
    for (int s = 0; s < 5; s++)
#pragma unroll
        for (int c = 0; c < 6; c++) TA[s][c] = 0.f;

    const float* rowp = x + base + (long)(Y0 - 3) * IMG + (cx - 4);
    // prime: rows Y0-3 -> slot 3, Y0-2 -> slot 4 (top/mid for first edge row)
    LOADROW(R[3], Y0 - 3);
    LOADROW(R[4], Y0 - 2);

    float* op = out + base + (long)(Y0 - 4) * IMG + cx;

    for (int tt = 0; tt < 70; tt += 5) {
        STEP(0, 3, 4, 1, 2, 3, 4);
        STEP(1, 4, 0, 2, 3, 4, 0);
        STEP(2, 0, 1, 3, 4, 0, 1);
        STEP(3, 1, 2, 4, 0, 1, 2);
        STEP(4, 2, 3, 0, 1, 2, 3);
    }
}

extern "C" void kernel_launch(void* const* d_in, const int* in_sizes, int n_in,
                              void* d_out, int out_size)
{
    const float* x = (const float*)d_in[0];
    float* out = (float*)d_out;
    const int planes = in_sizes[0] / (IMG * IMG);   // 64*3 = 192

    dim3 grid(IMG / BAND, planes);                  // (8, 192)
    residual_feature_kernel<<<grid, NTH>>>(x, out);
}